// round 1
// baseline (speedup 1.0000x reference)
#include <cuda_runtime.h>

#define NODES_MAX 50176
#define NEG_SLOPE 0.01f

// Scratch (no cudaMalloc allowed): per-node transformed features + attention scalars
__device__ float g_T[NODES_MAX * 128];   // T[n] = src_h[n] @ W + b
__device__ float g_p[NODES_MAX];         // p[n] = T[n] . Wa_z
__device__ float g_q[NODES_MAX];         // q[n] = self_h[n] . Wa_s

// ---- packed f32x2 helpers (2x fp32 FMA throughput on sm_103a) ----
__device__ __forceinline__ unsigned long long pk2(float x, float y) {
    unsigned long long r;
    asm("mov.b64 %0, {%1,%2};" : "=l"(r) : "f"(x), "f"(y));
    return r;
}
__device__ __forceinline__ void fma2(unsigned long long& d, unsigned long long a, unsigned long long b) {
    asm("fma.rn.f32x2 %0, %1, %2, %0;" : "+l"(d) : "l"(a), "l"(b));
}
__device__ __forceinline__ float2 up2(unsigned long long v) {
    float lo, hi;
    asm("mov.b64 {%0,%1}, %2;" : "=f"(lo), "=f"(hi) : "l"(v));
    return make_float2(lo, hi);
}

// ============================================================================
// Kernel 1: per-node GEMM  T = src_h @ W + b   (+ fused p, q dot products)
// Block: 256 threads, 128 node-rows, full N=128, K tiled by 32.
// Thread tile: 4 rows x 16 cols (cols split: tx*8..+7 and 64+tx*8..+7 to keep
// shared W loads bank-conflict-free).
// ============================================================================
__global__ __launch_bounds__(256, 2)
void node_gemm_kernel(const float* __restrict__ src_h,
                      const float* __restrict__ self_h,
                      const float* __restrict__ W,
                      const float* __restrict__ b,
                      const float* __restrict__ attn_W,
                      int n_nodes)
{
    __shared__ float As[128][33];     // padded: conflict-free row reads
    __shared__ float Ws[32][128];
    __shared__ float sWaZ[128];
    __shared__ float sWaS[128];
    __shared__ float sB[128];

    const int tid  = threadIdx.x;
    const int row0 = blockIdx.x * 128;

    if (tid < 128) {
        sWaZ[tid] = attn_W[tid];
        sWaS[tid] = attn_W[128 + tid];
        sB[tid]   = b[tid];
    }

    const int tx = tid & 7;    // 8 col-groups
    const int ty = tid >> 3;   // 32 row-groups of 4 rows
    const int c0 = tx * 8;     // first col block
    const int c1 = 64 + tx * 8;

    unsigned long long acc[4][8];
#pragma unroll
    for (int j = 0; j < 4; j++)
#pragma unroll
        for (int p = 0; p < 8; p++) acc[j][p] = 0ull;

    for (int kt = 0; kt < 4; kt++) {
        // stage A tile: 128 rows x 32 cols
#pragma unroll
        for (int l = 0; l < 4; l++) {
            int idx = tid + l * 256;           // 0..1023 float4 slots
            int r   = idx >> 3;
            int c4  = (idx & 7) * 4;
            int row = row0 + r;
            float4 v = make_float4(0.f, 0.f, 0.f, 0.f);
            if (row < n_nodes)
                v = *(const float4*)&src_h[(size_t)row * 128 + kt * 32 + c4];
            As[r][c4 + 0] = v.x; As[r][c4 + 1] = v.y;
            As[r][c4 + 2] = v.z; As[r][c4 + 3] = v.w;
        }
        // stage W tile: 32 rows x 128 cols
#pragma unroll
        for (int l = 0; l < 4; l++) {
            int idx = tid + l * 256;
            int r   = idx >> 5;
            int c4  = (idx & 31) * 4;
            float4 v = *(const float4*)&W[(size_t)(kt * 32 + r) * 128 + c4];
            *(float4*)&Ws[r][c4] = v;
        }
        __syncthreads();

#pragma unroll
        for (int k = 0; k < 32; k++) {
            unsigned long long pa[4];
#pragma unroll
            for (int j = 0; j < 4; j++) {
                float a = As[ty * 4 + j][k];
                pa[j] = pk2(a, a);
            }
            union { float4 f; unsigned long long u[2]; } w0, w1, w2, w3;
            w0.f = *(float4*)&Ws[k][c0];
            w1.f = *(float4*)&Ws[k][c0 + 4];
            w2.f = *(float4*)&Ws[k][c1];
            w3.f = *(float4*)&Ws[k][c1 + 4];
#pragma unroll
            for (int j = 0; j < 4; j++) {
                fma2(acc[j][0], pa[j], w0.u[0]);
                fma2(acc[j][1], pa[j], w0.u[1]);
                fma2(acc[j][2], pa[j], w1.u[0]);
                fma2(acc[j][3], pa[j], w1.u[1]);
                fma2(acc[j][4], pa[j], w2.u[0]);
                fma2(acc[j][5], pa[j], w2.u[1]);
                fma2(acc[j][6], pa[j], w3.u[0]);
                fma2(acc[j][7], pa[j], w3.u[1]);
            }
        }
        __syncthreads();
    }

    // epilogue: bias add, store T, fused p = T . Wa_z  (reduce over 8 tx lanes)
#pragma unroll
    for (int j = 0; j < 4; j++) {
        int row = row0 + ty * 4 + j;
        float part = 0.f;
        float2 vals[8];
#pragma unroll
        for (int p = 0; p < 8; p++) {
            int c = (p < 4) ? (c0 + 2 * p) : (c1 + 2 * (p - 4));
            float2 v = up2(acc[j][p]);
            v.x += sB[c];
            v.y += sB[c + 1];
            vals[p] = v;
            part += v.x * sWaZ[c] + v.y * sWaZ[c + 1];
        }
        part += __shfl_xor_sync(0xffffffffu, part, 1);
        part += __shfl_xor_sync(0xffffffffu, part, 2);
        part += __shfl_xor_sync(0xffffffffu, part, 4);
        if (row < n_nodes) {
            float2* trow = (float2*)&g_T[(size_t)row * 128];
#pragma unroll
            for (int p = 0; p < 8; p++) {
                int c = (p < 4) ? (c0 + 2 * p) : (c1 + 2 * (p - 4));
                trow[c >> 1] = vals[p];
            }
            if (tx == 0) g_p[row] = part;
        }
    }

    // fused q[n] = self_h[n] . Wa_s  (one warp per row, 8 warps x 16 rows)
    const int wid  = tid >> 5;
    const int lane = tid & 31;
    for (int r = wid; r < 128; r += 8) {
        int row = row0 + r;
        if (row < n_nodes) {
            float4 v = *(const float4*)&self_h[(size_t)row * 128 + lane * 4];
            float s = v.x * sWaS[lane * 4 + 0] + v.y * sWaS[lane * 4 + 1]
                    + v.z * sWaS[lane * 4 + 2] + v.w * sWaS[lane * 4 + 3];
            s += __shfl_xor_sync(0xffffffffu, s, 16);
            s += __shfl_xor_sync(0xffffffffu, s, 8);
            s += __shfl_xor_sync(0xffffffffu, s, 4);
            s += __shfl_xor_sync(0xffffffffu, s, 2);
            s += __shfl_xor_sync(0xffffffffu, s, 1);
            if (lane == 0) g_q[row] = s;
        }
    }
}

// ============================================================================
// Kernel 2: edge streaming. One warp per edge: gather T row (L2-resident),
// stream z1, scalar attention score e.
// ============================================================================
__global__ __launch_bounds__(256)
void edge_kernel(const int* __restrict__ src_idx,
                 const int* __restrict__ dst_idx,
                 const float* __restrict__ attn_b,
                 float* __restrict__ z1,
                 float* __restrict__ e,
                 int n_edges)
{
    int eidx = blockIdx.x * 8 + (threadIdx.x >> 5);
    int lane = threadIdx.x & 31;
    if (eidx >= n_edges) return;

    int s = __ldg(&src_idx[eidx]);
    float4 v = ((const float4*)g_T)[(size_t)s * 32 + lane];
    ((float4*)z1)[(size_t)eidx * 32 + lane] = v;

    if (lane == 0) {
        int d = __ldg(&dst_idx[eidx]);
        float a = g_p[s] + g_q[d] + attn_b[0];
        e[eidx] = (a >= 0.f) ? a : NEG_SLOPE * a;
    }
}

// ============================================================================
extern "C" void kernel_launch(void* const* d_in, const int* in_sizes, int n_in,
                              void* d_out, int out_size)
{
    const float* src_h  = (const float*)d_in[0];
    const float* self_h = (const float*)d_in[1];
    const int*   src_idx = (const int*)d_in[2];
    const int*   dst_idx = (const int*)d_in[3];
    const float* W      = (const float*)d_in[4];
    const float* b      = (const float*)d_in[5];
    const float* attn_W = (const float*)d_in[6];
    const float* attn_b = (const float*)d_in[7];

    int n_nodes = in_sizes[0] / 128;
    int n_edges = in_sizes[2];

    float* z1 = (float*)d_out;                       // n_edges x 128
    float* e  = z1 + (size_t)n_edges * 128;          // n_edges

    node_gemm_kernel<<<(n_nodes + 127) / 128, 256>>>(src_h, self_h, W, b, attn_W, n_nodes);
    edge_kernel<<<(n_edges + 7) / 8, 256>>>(src_idx, dst_idx, attn_b, z1, e, n_edges);
}

// round 2
// speedup vs baseline: 1.3876x; 1.3876x over previous
#include <cuda_runtime.h>

#define NODES_MAX 50176
#define NEG_SLOPE 0.01f

// Scratch (no cudaMalloc allowed)
__device__ float g_T[NODES_MAX * 128];   // T[n] = src_h[n] @ W + b
__device__ float g_p[NODES_MAX];         // p[n] = T[n] . Wa_z
__device__ float g_q[NODES_MAX];         // q[n] = self_h[n] . Wa_s

// ---- packed f32x2 helpers (2x fp32 FMA throughput on sm_103a) ----
__device__ __forceinline__ unsigned long long pk2(float x, float y) {
    unsigned long long r;
    asm("mov.b64 %0, {%1,%2};" : "=l"(r) : "f"(x), "f"(y));
    return r;
}
__device__ __forceinline__ void fma2(unsigned long long& d, unsigned long long a, unsigned long long b) {
    asm("fma.rn.f32x2 %0, %1, %2, %0;" : "+l"(d) : "l"(a), "l"(b));
}
__device__ __forceinline__ float2 up2(unsigned long long v) {
    float lo, hi;
    asm("mov.b64 {%0,%1}, %2;" : "=f"(lo), "=f"(hi) : "l"(v));
    return make_float2(lo, hi);
}

// ============================================================================
// Kernel 1: per-node GEMM  T = src_h @ W + b  (+ fused p, q dot products)
// 64-row tile, 256 threads (16 tx x 16 ty), thread tile 4 rows x 8 cols.
// Accumulators: 16 packed f32x2 (32 regs) -> no spill, 3+ blocks/SM.
// ============================================================================
__global__ __launch_bounds__(256)
void node_gemm_kernel(const float* __restrict__ src_h,
                      const float* __restrict__ self_h,
                      const float* __restrict__ W,
                      const float* __restrict__ b,
                      const float* __restrict__ attn_W,
                      int n_nodes)
{
    __shared__ float As[64][33];      // padded
    __shared__ float Ws[32][128];
    __shared__ float sWaZ[128];
    __shared__ float sWaS[128];
    __shared__ float sB[128];

    const int tid  = threadIdx.x;
    const int row0 = blockIdx.x * 64;

    if (tid < 128) {
        sWaZ[tid] = attn_W[tid];
        sWaS[tid] = attn_W[128 + tid];
        sB[tid]   = b[tid];
    }

    const int tx = tid & 15;          // 16 col-groups of 8 cols
    const int ty = tid >> 4;          // 16 row-groups of 4 rows
    const int c0 = tx * 8;

    unsigned long long acc[4][4];
#pragma unroll
    for (int j = 0; j < 4; j++)
#pragma unroll
        for (int p = 0; p < 4; p++) acc[j][p] = 0ull;

    for (int kt = 0; kt < 4; kt++) {
        // stage A tile: 64 rows x 32 cols (512 float4, 2 per thread)
#pragma unroll
        for (int l = 0; l < 2; l++) {
            int idx = tid + l * 256;
            int r   = idx >> 3;
            int c4  = (idx & 7) * 4;
            int row = row0 + r;
            float4 v = make_float4(0.f, 0.f, 0.f, 0.f);
            if (row < n_nodes)
                v = *(const float4*)&src_h[(size_t)row * 128 + kt * 32 + c4];
            As[r][c4 + 0] = v.x; As[r][c4 + 1] = v.y;
            As[r][c4 + 2] = v.z; As[r][c4 + 3] = v.w;
        }
        // stage W tile: 32 rows x 128 cols (1024 float4, 4 per thread)
#pragma unroll
        for (int l = 0; l < 4; l++) {
            int idx = tid + l * 256;
            int r   = idx >> 5;
            int c4  = (idx & 31) * 4;
            *(float4*)&Ws[r][c4] = *(const float4*)&W[(size_t)(kt * 32 + r) * 128 + c4];
        }
        __syncthreads();

#pragma unroll
        for (int k = 0; k < 32; k++) {
            union { float4 f; unsigned long long u[2]; } w0, w1;
            w0.f = *(float4*)&Ws[k][c0];
            w1.f = *(float4*)&Ws[k][c0 + 4];
            unsigned long long pa[4];
#pragma unroll
            for (int j = 0; j < 4; j++) {
                float a = As[ty * 4 + j][k];
                pa[j] = pk2(a, a);
            }
#pragma unroll
            for (int j = 0; j < 4; j++) {
                fma2(acc[j][0], pa[j], w0.u[0]);
                fma2(acc[j][1], pa[j], w0.u[1]);
                fma2(acc[j][2], pa[j], w1.u[0]);
                fma2(acc[j][3], pa[j], w1.u[1]);
            }
        }
        __syncthreads();
    }

    // epilogue: bias add, store T, fused p = T . Wa_z (reduce across 16 tx lanes)
#pragma unroll
    for (int j = 0; j < 4; j++) {
        int row = row0 + ty * 4 + j;
        float part = 0.f;
        float2 vals[4];
#pragma unroll
        for (int p = 0; p < 4; p++) {
            int c = c0 + 2 * p;
            float2 v = up2(acc[j][p]);
            v.x += sB[c];
            v.y += sB[c + 1];
            vals[p] = v;
            part += v.x * sWaZ[c] + v.y * sWaZ[c + 1];
        }
        part += __shfl_xor_sync(0xffffffffu, part, 1);
        part += __shfl_xor_sync(0xffffffffu, part, 2);
        part += __shfl_xor_sync(0xffffffffu, part, 4);
        part += __shfl_xor_sync(0xffffffffu, part, 8);
        if (row < n_nodes) {
            float2* trow = (float2*)&g_T[(size_t)row * 128];
#pragma unroll
            for (int p = 0; p < 4; p++)
                trow[(c0 >> 1) + p] = vals[p];
            if (tx == 0) g_p[row] = part;
        }
    }

    // fused q[n] = self_h[n] . Wa_s  (one warp per row)
    const int wid  = tid >> 5;
    const int lane = tid & 31;
    for (int r = wid; r < 64; r += 8) {
        int row = row0 + r;
        if (row < n_nodes) {
            float4 v = *(const float4*)&self_h[(size_t)row * 128 + lane * 4];
            float s = v.x * sWaS[lane * 4 + 0] + v.y * sWaS[lane * 4 + 1]
                    + v.z * sWaS[lane * 4 + 2] + v.w * sWaS[lane * 4 + 3];
            s += __shfl_xor_sync(0xffffffffu, s, 16);
            s += __shfl_xor_sync(0xffffffffu, s, 8);
            s += __shfl_xor_sync(0xffffffffu, s, 4);
            s += __shfl_xor_sync(0xffffffffu, s, 2);
            s += __shfl_xor_sync(0xffffffffu, s, 1);
            if (lane == 0) g_q[row] = s;
        }
    }
}

// ============================================================================
// Kernel 2: edge streaming. Persistent warps, 4 edges per warp-iteration
// (MLP=4 independent gathers), streaming stores (.cs) keep T L2-resident.
// ============================================================================
__global__ __launch_bounds__(256)
void edge_kernel(const int* __restrict__ src_idx,
                 const int* __restrict__ dst_idx,
                 const float* __restrict__ attn_b,
                 float* __restrict__ z1,
                 float* __restrict__ e,
                 int n_edges)
{
    const int warp   = blockIdx.x * 8 + (threadIdx.x >> 5);
    const int lane   = threadIdx.x & 31;
    const int nwarps = gridDim.x * 8;
    const float ab   = __ldg(attn_b);

    for (int base = warp * 4; base < n_edges; base += nwarps * 4) {
        const int n = min(4, n_edges - base);
        int s[4];
#pragma unroll
        for (int j = 0; j < 4; j++)
            s[j] = (j < n) ? __ldg(&src_idx[base + j]) : 0;

        float4 v[4];
#pragma unroll
        for (int j = 0; j < 4; j++)
            v[j] = __ldg((const float4*)&g_T[(size_t)s[j] * 128] + lane);

#pragma unroll
        for (int j = 0; j < 4; j++)
            if (j < n)
                __stcs(((float4*)z1) + (size_t)(base + j) * 32 + lane, v[j]);

        // attention score: 4 lanes handle 4 edges (parallel p/q gathers)
        if (lane < n) {
            int ej = base + lane;
            int ss = __ldg(&src_idx[ej]);
            int dd = __ldg(&dst_idx[ej]);
            float a = g_p[ss] + g_q[dd] + ab;
            e[ej] = (a >= 0.f) ? a : NEG_SLOPE * a;
        }
    }
}

// ============================================================================
extern "C" void kernel_launch(void* const* d_in, const int* in_sizes, int n_in,
                              void* d_out, int out_size)
{
    const float* src_h   = (const float*)d_in[0];
    const float* self_h  = (const float*)d_in[1];
    const int*   src_idx = (const int*)d_in[2];
    const int*   dst_idx = (const int*)d_in[3];
    const float* W       = (const float*)d_in[4];
    const float* b       = (const float*)d_in[5];
    const float* attn_W  = (const float*)d_in[6];
    const float* attn_b  = (const float*)d_in[7];

    int n_nodes = in_sizes[0] / 128;
    int n_edges = in_sizes[2];

    float* z1 = (float*)d_out;                       // n_edges x 128
    float* e  = z1 + (size_t)n_edges * 128;          // n_edges

    node_gemm_kernel<<<(n_nodes + 63) / 64, 256>>>(src_h, self_h, W, b, attn_W, n_nodes);

    int eblocks = (n_edges + 31) / 32;               // 1 iteration if grid fits
    if (eblocks > 2368) eblocks = 2368;              // persistent: 16 blocks/SM
    edge_kernel<<<eblocks, 256>>>(src_idx, dst_idx, attn_b, z1, e, n_edges);
}

// round 5
// speedup vs baseline: 1.7979x; 1.2957x over previous
#include <cuda_runtime.h>
#include <cuda_bf16.h>
#include <cstdint>

#define NODES_MAX 50176
#define NEG_SLOPE 0.01f

// Scratch (no cudaMalloc allowed)
__device__ float g_T[NODES_MAX * 128];            // T[n] = src_h[n] @ W + b
__device__ float g_p[NODES_MAX];                  // p[n] = T[n] . Wa_z
__device__ float g_q[NODES_MAX];                  // q[n] = self_h[n] . Wa_s
__device__ __nv_bfloat16 g_Wt_hi[128 * 128];      // W^T split-high  [n][k]
__device__ __nv_bfloat16 g_Wt_lo[128 * 128];      // W^T split-low   [n][k]

__device__ __forceinline__ void ldm4(uint32_t& r0, uint32_t& r1, uint32_t& r2, uint32_t& r3,
                                     uint32_t addr) {
    asm volatile("ldmatrix.sync.aligned.m8n8.x4.shared.b16 {%0,%1,%2,%3}, [%4];"
                 : "=r"(r0), "=r"(r1), "=r"(r2), "=r"(r3) : "r"(addr));
}
__device__ __forceinline__ void mma_bf16(float* d, const uint32_t* a, const uint32_t* b) {
    asm volatile("mma.sync.aligned.m16n8k16.row.col.f32.bf16.bf16.f32 "
                 "{%0,%1,%2,%3}, {%4,%5,%6,%7}, {%8,%9}, {%0,%1,%2,%3};"
                 : "+f"(d[0]), "+f"(d[1]), "+f"(d[2]), "+f"(d[3])
                 : "r"(a[0]), "r"(a[1]), "r"(a[2]), "r"(a[3]), "r"(b[0]), "r"(b[1]));
}
__device__ __forceinline__ uint32_t smem_u32(const void* p) {
    uint32_t a;
    asm("{ .reg .u64 t; cvta.to.shared.u64 t, %1; cvt.u32.u64 %0, t; }" : "=r"(a) : "l"(p));
    return a;
}
__device__ __forceinline__ uint32_t pkbf(float a, float b) {
    __nv_bfloat162 t = __floats2bfloat162_rn(a, b);
    return *(uint32_t*)&t;
}

// ============================================================================
// Kernel 0: split W into W^T hi/lo bf16 (tiny, one-shot)
// ============================================================================
__global__ void prep_w_kernel(const float* __restrict__ W) {
    int idx = blockIdx.x * 256 + threadIdx.x;       // idx = n*128 + k
    if (idx >= 128 * 128) return;
    int n = idx >> 7, k = idx & 127;
    float v = W[k * 128 + n];
    __nv_bfloat16 hi = __float2bfloat16(v);
    g_Wt_hi[idx] = hi;
    g_Wt_lo[idx] = __float2bfloat16(v - __bfloat162float(hi));
}

// ============================================================================
// Kernel 1: node GEMM on HMMA.  T = src_h @ W + b   (+ fused p, q scalars)
// 128 rows/CTA, 256 threads (8 warps: 2 M x 4 N). bf16 2-term split, 3 passes.
// SMEM tiles: row stride 272B (17x16B) -> conflict-free ldmatrix & stores.
// ============================================================================
#define TSTRIDE 272                       // bytes per SMEM tile row (136 bf16)
#define SM_PP   1536                      // ppart[4][128] floats (2KB)
#define SM_HDR  4096
#define SM_AHI  (SM_HDR)
#define SM_ALO  (SM_AHI + 128 * TSTRIDE)
#define SM_BHI  (SM_ALO + 128 * TSTRIDE)
#define SM_BLO  (SM_BHI + 128 * TSTRIDE)
#define SM_TOTAL (SM_BLO + 128 * TSTRIDE) // 143360

__global__ __launch_bounds__(256)
void node_gemm_kernel(const float* __restrict__ src_h,
                      const float* __restrict__ self_h,
                      const float* __restrict__ b,
                      const float* __restrict__ attn_W,
                      int n_nodes)
{
    extern __shared__ char smem[];
    const uint32_t sb = smem_u32(smem);
    const int tid  = threadIdx.x;
    const int wid  = tid >> 5;
    const int lane = tid & 31;
    const int row0 = blockIdx.x * 128;

    float* sWaZ  = (float*)(smem + 0);
    float* sWaS  = (float*)(smem + 512);
    float* sB    = (float*)(smem + 1024);
    float* ppart = (float*)(smem + SM_PP);      // [4][128]
    if (tid < 128) {
        sWaZ[tid] = attn_W[tid];
        sWaS[tid] = attn_W[128 + tid];
        sB[tid]   = b[tid];
    }

    // ---- stage A: src_h rows -> bf16 hi/lo (dense, coalesced) ----
    // 128 rows x 32 float4 = 4096 float4, 16 per thread
#pragma unroll
    for (int l = 0; l < 16; l++) {
        int i  = tid + l * 256;
        int r  = i >> 5;
        int c  = (i & 31) * 4;
        int row = row0 + r;
        float4 v = make_float4(0.f, 0.f, 0.f, 0.f);
        if (row < n_nodes)
            v = *(const float4*)&src_h[(size_t)row * 128 + c];
        __nv_bfloat16 h0 = __float2bfloat16(v.x), h1 = __float2bfloat16(v.y);
        __nv_bfloat16 h2 = __float2bfloat16(v.z), h3 = __float2bfloat16(v.w);
        __nv_bfloat162 p0; p0.x = h0; p0.y = h1;
        __nv_bfloat162 p1; p1.x = h2; p1.y = h3;
        *(uint2*)(smem + SM_AHI + r * TSTRIDE + c * 2) =
            make_uint2(*(uint32_t*)&p0, *(uint32_t*)&p1);
        *(uint2*)(smem + SM_ALO + r * TSTRIDE + c * 2) = make_uint2(
            pkbf(v.x - __bfloat162float(h0), v.y - __bfloat162float(h1)),
            pkbf(v.z - __bfloat162float(h2), v.w - __bfloat162float(h3)));
    }
    // ---- stage B: W^T hi/lo bf16 (dense, coalesced) ----
    // 128 rows x 32 uint2 = 4096 uint2, 16 per thread
#pragma unroll
    for (int l = 0; l < 16; l++) {
        int i  = tid + l * 256;
        int r  = i >> 5;
        int c8 = i & 31;
        *(uint2*)(smem + SM_BHI + r * TSTRIDE + c8 * 8) = ((const uint2*)g_Wt_hi)[r * 32 + c8];
        *(uint2*)(smem + SM_BLO + r * TSTRIDE + c8 * 8) = ((const uint2*)g_Wt_lo)[r * 32 + c8];
    }
    __syncthreads();

    // ---- HMMA mainloop: 8 k-steps x 3 split-passes x (4 mt x 2 nt x 2 s) ----
    const int wm = (wid >> 2) * 64;           // warp M offset (0 or 64)
    const int wn = (wid & 3) * 32;            // warp N offset

    float acc[4][2][2][4];
#pragma unroll
    for (int mt = 0; mt < 4; mt++)
#pragma unroll
        for (int nt = 0; nt < 2; nt++)
#pragma unroll
            for (int s = 0; s < 2; s++)
#pragma unroll
                for (int g = 0; g < 4; g++) acc[mt][nt][s][g] = 0.f;

    const int a_row = (lane & 15);
    const int a_col = (lane >> 4) * 8;
    const int b_row = (lane & 7) + ((lane >> 4) << 3);
    const int b_col = ((lane >> 3) & 1) * 8;

#pragma unroll
    for (int ks = 0; ks < 8; ks++) {
        const int k0 = ks * 16;
        uint32_t Ah[4][4], Al[4][4], Bh[2][4], Bl[2][4];
#pragma unroll
        for (int mt = 0; mt < 4; mt++) {
            uint32_t off = (uint32_t)((wm + mt * 16 + a_row) * TSTRIDE + (k0 + a_col) * 2);
            ldm4(Ah[mt][0], Ah[mt][1], Ah[mt][2], Ah[mt][3], sb + SM_AHI + off);
            ldm4(Al[mt][0], Al[mt][1], Al[mt][2], Al[mt][3], sb + SM_ALO + off);
        }
#pragma unroll
        for (int nt = 0; nt < 2; nt++) {
            uint32_t off = (uint32_t)((wn + nt * 16 + b_row) * TSTRIDE + (k0 + b_col) * 2);
            ldm4(Bh[nt][0], Bh[nt][1], Bh[nt][2], Bh[nt][3], sb + SM_BHI + off);
            ldm4(Bl[nt][0], Bl[nt][1], Bl[nt][2], Bl[nt][3], sb + SM_BLO + off);
        }
#pragma unroll
        for (int mt = 0; mt < 4; mt++)
#pragma unroll
            for (int nt = 0; nt < 2; nt++)
#pragma unroll
                for (int s = 0; s < 2; s++) {
                    mma_bf16(acc[mt][nt][s], Ah[mt], &Bh[nt][s * 2]);   // hi*hi
                    mma_bf16(acc[mt][nt][s], Ah[mt], &Bl[nt][s * 2]);   // hi*lo
                    mma_bf16(acc[mt][nt][s], Al[mt], &Bh[nt][s * 2]);   // lo*hi
                }
    }

    // ---- epilogue: bias, direct g_T stores, per-warp partial p-dot ----
    float pacc[4][2];
#pragma unroll
    for (int mt = 0; mt < 4; mt++) { pacc[mt][0] = 0.f; pacc[mt][1] = 0.f; }

#pragma unroll
    for (int mt = 0; mt < 4; mt++)
#pragma unroll
        for (int nt = 0; nt < 2; nt++)
#pragma unroll
            for (int s = 0; s < 2; s++) {
                const int c = wn + nt * 16 + s * 8 + (lane & 3) * 2;
#pragma unroll
                for (int h = 0; h < 2; h++) {
                    const int r = wm + mt * 16 + (lane >> 2) + h * 8;
                    float v0 = acc[mt][nt][s][h * 2 + 0] + sB[c];
                    float v1 = acc[mt][nt][s][h * 2 + 1] + sB[c + 1];
                    pacc[mt][h] += v0 * sWaZ[c] + v1 * sWaZ[c + 1];
                    if (row0 + r < n_nodes)
                        *(float2*)&g_T[(size_t)(row0 + r) * 128 + c] = make_float2(v0, v1);
                }
            }
    // reduce p within warp quad, park per-warp partial in smem
#pragma unroll
    for (int mt = 0; mt < 4; mt++)
#pragma unroll
        for (int h = 0; h < 2; h++) {
            float p = pacc[mt][h];
            p += __shfl_xor_sync(0xffffffffu, p, 1);
            p += __shfl_xor_sync(0xffffffffu, p, 2);
            const int r = wm + mt * 16 + (lane >> 2) + h * 8;
            if ((lane & 3) == 0) ppart[(wid & 3) * 128 + r] = p;
        }
    __syncthreads();
    // sum the 4 N-warp partials per row
    if (tid < 128) {
        int row = row0 + tid;
        if (row < n_nodes)
            g_p[row] = ppart[tid] + ppart[128 + tid] + ppart[256 + tid] + ppart[384 + tid];
    }

    // ---- q[n] = self_h[n] . Wa_s  (one warp per row, coalesced) ----
    for (int r = wid; r < 128; r += 8) {
        int row = row0 + r;
        if (row < n_nodes) {
            float4 v = *(const float4*)&self_h[(size_t)row * 128 + lane * 4];
            float s = v.x * sWaS[lane * 4 + 0] + v.y * sWaS[lane * 4 + 1]
                    + v.z * sWaS[lane * 4 + 2] + v.w * sWaS[lane * 4 + 3];
            s += __shfl_xor_sync(0xffffffffu, s, 16);
            s += __shfl_xor_sync(0xffffffffu, s, 8);
            s += __shfl_xor_sync(0xffffffffu, s, 4);
            s += __shfl_xor_sync(0xffffffffu, s, 2);
            s += __shfl_xor_sync(0xffffffffu, s, 1);
            if (lane == 0) g_q[row] = s;
        }
    }
}

// ============================================================================
// Kernel 2: edge streaming. Persistent warps, 8 edges / warp-iter (MLP=8),
// streaming stores keep T L2-resident.
// ============================================================================
__global__ __launch_bounds__(256)
void edge_kernel(const int* __restrict__ src_idx,
                 const int* __restrict__ dst_idx,
                 const float* __restrict__ attn_b,
                 float* __restrict__ z1,
                 float* __restrict__ e,
                 int n_edges)
{
    const int warp   = blockIdx.x * 8 + (threadIdx.x >> 5);
    const int lane   = threadIdx.x & 31;
    const int nwarps = gridDim.x * 8;
    const float ab   = __ldg(attn_b);

    for (int base = warp * 8; base < n_edges; base += nwarps * 8) {
        const int n = min(8, n_edges - base);
        int s[8];
#pragma unroll
        for (int j = 0; j < 8; j++)
            s[j] = (j < n) ? __ldg(&src_idx[base + j]) : 0;

        float4 v[8];
#pragma unroll
        for (int j = 0; j < 8; j++)
            v[j] = __ldg((const float4*)&g_T[(size_t)s[j] * 128] + lane);

#pragma unroll
        for (int j = 0; j < 8; j++)
            if (j < n)
                __stcs(((float4*)z1) + (size_t)(base + j) * 32 + lane, v[j]);

        if (lane < n) {
            int ej = base + lane;
            int ss = __ldg(&src_idx[ej]);
            int dd = __ldg(&dst_idx[ej]);
            float a = g_p[ss] + g_q[dd] + ab;
            e[ej] = (a >= 0.f) ? a : NEG_SLOPE * a;
        }
    }
}

// ============================================================================
extern "C" void kernel_launch(void* const* d_in, const int* in_sizes, int n_in,
                              void* d_out, int out_size)
{
    const float* src_h   = (const float*)d_in[0];
    const float* self_h  = (const float*)d_in[1];
    const int*   src_idx = (const int*)d_in[2];
    const int*   dst_idx = (const int*)d_in[3];
    const float* W       = (const float*)d_in[4];
    const float* b       = (const float*)d_in[5];
    const float* attn_W  = (const float*)d_in[6];
    const float* attn_b  = (const float*)d_in[7];

    int n_nodes = in_sizes[0] / 128;
    int n_edges = in_sizes[2];

    float* z1 = (float*)d_out;                    // n_edges x 128
    float* e  = z1 + (size_t)n_edges * 128;       // n_edges

    cudaFuncSetAttribute(node_gemm_kernel,
                         cudaFuncAttributeMaxDynamicSharedMemorySize, SM_TOTAL);

    prep_w_kernel<<<64, 256>>>(W);
    node_gemm_kernel<<<(n_nodes + 127) / 128, 256, SM_TOTAL>>>(src_h, self_h, b, attn_W, n_nodes);
    edge_kernel<<<1184, 256>>>(src_idx, dst_idx, attn_b, z1, e, n_edges);
}

// round 6
// speedup vs baseline: 2.0781x; 1.1558x over previous
#include <cuda_runtime.h>
#include <cuda_bf16.h>
#include <cstdint>

#define NODES_MAX 50176
#define NEG_SLOPE 0.01f

// Scratch (no cudaMalloc allowed)
__device__ float g_T[NODES_MAX * 128];            // T[n] = src_h[n] @ W + b
__device__ float g_p[NODES_MAX];                  // p[n] = T[n] . Wa_z
__device__ float g_q[NODES_MAX];                  // q[n] = self_h[n] . Wa_s
__device__ __nv_bfloat16 g_Wt_hi[128 * 128];      // W^T split-high  [n][k]
__device__ __nv_bfloat16 g_Wt_lo[128 * 128];      // W^T split-low   [n][k]

__device__ __forceinline__ void ldm4(uint32_t& r0, uint32_t& r1, uint32_t& r2, uint32_t& r3,
                                     uint32_t addr) {
    asm volatile("ldmatrix.sync.aligned.m8n8.x4.shared.b16 {%0,%1,%2,%3}, [%4];"
                 : "=r"(r0), "=r"(r1), "=r"(r2), "=r"(r3) : "r"(addr));
}
__device__ __forceinline__ void mma_bf16(float* d, const uint32_t* a, const uint32_t* b) {
    asm volatile("mma.sync.aligned.m16n8k16.row.col.f32.bf16.bf16.f32 "
                 "{%0,%1,%2,%3}, {%4,%5,%6,%7}, {%8,%9}, {%0,%1,%2,%3};"
                 : "+f"(d[0]), "+f"(d[1]), "+f"(d[2]), "+f"(d[3])
                 : "r"(a[0]), "r"(a[1]), "r"(a[2]), "r"(a[3]), "r"(b[0]), "r"(b[1]));
}
__device__ __forceinline__ uint32_t smem_u32(const void* p) {
    uint32_t a;
    asm("{ .reg .u64 t; cvta.to.shared.u64 t, %1; cvt.u32.u64 %0, t; }" : "=r"(a) : "l"(p));
    return a;
}
__device__ __forceinline__ void cpasync16(uint32_t dst, const void* src) {
    asm volatile("cp.async.cg.shared.global [%0], [%1], 16;" :: "r"(dst), "l"(src) : "memory");
}
__device__ __forceinline__ uint32_t pkbf(float a, float b) {
    __nv_bfloat162 t = __floats2bfloat162_rn(a, b);
    return *(uint32_t*)&t;
}

// ============================================================================
// Kernel 0: split W into W^T hi/lo bf16 (tiny, one-shot)
// ============================================================================
__global__ void prep_w_kernel(const float* __restrict__ W) {
    int idx = blockIdx.x * 256 + threadIdx.x;       // idx = n*128 + k
    if (idx >= 128 * 128) return;
    int n = idx >> 7, k = idx & 127;
    float v = W[k * 128 + n];
    __nv_bfloat16 hi = __float2bfloat16(v);
    g_Wt_hi[idx] = hi;
    g_Wt_lo[idx] = __float2bfloat16(v - __bfloat162float(hi));
}

// ============================================================================
// Kernel 1: node GEMM on HMMA.  T = src_h @ W + b   (+ fused p, q scalars)
// 64 rows/CTA (2 CTAs/SM for cross-CTA latency overlap), 256 threads
// (8 warps: 2 M x 4 N, warp tile 32x32). bf16 2-term split, 3 mma passes.
// SMEM row stride 272B (17x16B) -> conflict-free ldmatrix & stores.
// B tiles staged via cp.async (bf16, no conversion needed).
// ============================================================================
#define TSTRIDE 272
#define SM_PP   1536                       // ppart[4][64] floats (1KB)
#define SM_HDR  4096
#define SM_AHI  (SM_HDR)                       // 64 x 272 = 17408
#define SM_ALO  (SM_AHI + 64 * TSTRIDE)
#define SM_BHI  (SM_ALO + 64 * TSTRIDE)        // 128 x 272 = 34816
#define SM_BLO  (SM_BHI + 128 * TSTRIDE)
#define SM_TOTAL (SM_BLO + 128 * TSTRIDE)      // 108544
 
__global__ __launch_bounds__(256)
void node_gemm_kernel(const float* __restrict__ src_h,
                      const float* __restrict__ self_h,
                      const float* __restrict__ b,
                      const float* __restrict__ attn_W,
                      int n_nodes)
{
    extern __shared__ char smem[];
    const uint32_t sb = smem_u32(smem);
    const int tid  = threadIdx.x;
    const int wid  = tid >> 5;
    const int lane = tid & 31;
    const int row0 = blockIdx.x * 64;

    float* sWaZ  = (float*)(smem + 0);
    float* sWaS  = (float*)(smem + 512);
    float* sB    = (float*)(smem + 1024);
    float* ppart = (float*)(smem + SM_PP);     // [4][64]
    if (tid < 128) {
        sWaZ[tid] = attn_W[tid];
        sWaS[tid] = attn_W[128 + tid];
        sB[tid]   = b[tid];
    }

    // ---- stage B via cp.async: 128 rows x 16 chunks x 2 tiles ----
#pragma unroll
    for (int l = 0; l < 8; l++) {
        int i = tid + l * 256;                 // 0..2047
        int r = i >> 4, c = i & 15;
        cpasync16(sb + SM_BHI + r * TSTRIDE + c * 16, (const char*)g_Wt_hi + r * 256 + c * 16);
        cpasync16(sb + SM_BLO + r * TSTRIDE + c * 16, (const char*)g_Wt_lo + r * 256 + c * 16);
    }
    asm volatile("cp.async.commit_group;" ::: "memory");

    // ---- stage A: 64 rows x 32 float4, convert fp32 -> bf16 hi/lo ----
#pragma unroll
    for (int l = 0; l < 8; l++) {
        int i  = tid + l * 256;                // 0..2047
        int r  = i >> 5;
        int c  = (i & 31) * 4;
        int row = row0 + r;
        float4 v = make_float4(0.f, 0.f, 0.f, 0.f);
        if (row < n_nodes)
            v = *(const float4*)&src_h[(size_t)row * 128 + c];
        __nv_bfloat16 h0 = __float2bfloat16(v.x), h1 = __float2bfloat16(v.y);
        __nv_bfloat16 h2 = __float2bfloat16(v.z), h3 = __float2bfloat16(v.w);
        __nv_bfloat162 p0; p0.x = h0; p0.y = h1;
        __nv_bfloat162 p1; p1.x = h2; p1.y = h3;
        *(uint2*)(smem + SM_AHI + r * TSTRIDE + c * 2) =
            make_uint2(*(uint32_t*)&p0, *(uint32_t*)&p1);
        *(uint2*)(smem + SM_ALO + r * TSTRIDE + c * 2) = make_uint2(
            pkbf(v.x - __bfloat162float(h0), v.y - __bfloat162float(h1)),
            pkbf(v.z - __bfloat162float(h2), v.w - __bfloat162float(h3)));
    }
    asm volatile("cp.async.wait_group 0;" ::: "memory");
    __syncthreads();

    // ---- HMMA mainloop ----
    const int wm = (wid >> 2) * 32;            // 0 or 32
    const int wn = (wid & 3) * 32;

    float acc[2][2][2][4];
#pragma unroll
    for (int mt = 0; mt < 2; mt++)
#pragma unroll
        for (int nt = 0; nt < 2; nt++)
#pragma unroll
            for (int s = 0; s < 2; s++)
#pragma unroll
                for (int g = 0; g < 4; g++) acc[mt][nt][s][g] = 0.f;

    const int a_row = (lane & 15);
    const int a_col = (lane >> 4) * 8;
    const int b_row = (lane & 7) + ((lane >> 4) << 3);
    const int b_col = ((lane >> 3) & 1) * 8;

#pragma unroll
    for (int ks = 0; ks < 8; ks++) {
        const int k0 = ks * 16;
        uint32_t Ah[2][4], Al[2][4], Bh[2][4], Bl[2][4];
#pragma unroll
        for (int mt = 0; mt < 2; mt++) {
            uint32_t off = (uint32_t)((wm + mt * 16 + a_row) * TSTRIDE + (k0 + a_col) * 2);
            ldm4(Ah[mt][0], Ah[mt][1], Ah[mt][2], Ah[mt][3], sb + SM_AHI + off);
            ldm4(Al[mt][0], Al[mt][1], Al[mt][2], Al[mt][3], sb + SM_ALO + off);
        }
#pragma unroll
        for (int nt = 0; nt < 2; nt++) {
            uint32_t off = (uint32_t)((wn + nt * 16 + b_row) * TSTRIDE + (k0 + b_col) * 2);
            ldm4(Bh[nt][0], Bh[nt][1], Bh[nt][2], Bh[nt][3], sb + SM_BHI + off);
            ldm4(Bl[nt][0], Bl[nt][1], Bl[nt][2], Bl[nt][3], sb + SM_BLO + off);
        }
#pragma unroll
        for (int mt = 0; mt < 2; mt++)
#pragma unroll
            for (int nt = 0; nt < 2; nt++)
#pragma unroll
                for (int s = 0; s < 2; s++) {
                    mma_bf16(acc[mt][nt][s], Ah[mt], &Bh[nt][s * 2]);   // hi*hi
                    mma_bf16(acc[mt][nt][s], Ah[mt], &Bl[nt][s * 2]);   // hi*lo
                    mma_bf16(acc[mt][nt][s], Al[mt], &Bh[nt][s * 2]);   // lo*hi
                }
    }

    // ---- epilogue: bias, direct g_T stores, per-warp partial p-dot ----
    float pacc[2][2];
#pragma unroll
    for (int mt = 0; mt < 2; mt++) { pacc[mt][0] = 0.f; pacc[mt][1] = 0.f; }

#pragma unroll
    for (int mt = 0; mt < 2; mt++)
#pragma unroll
        for (int nt = 0; nt < 2; nt++)
#pragma unroll
            for (int s = 0; s < 2; s++) {
                const int c = wn + nt * 16 + s * 8 + (lane & 3) * 2;
#pragma unroll
                for (int h = 0; h < 2; h++) {
                    const int r = wm + mt * 16 + (lane >> 2) + h * 8;
                    float v0 = acc[mt][nt][s][h * 2 + 0] + sB[c];
                    float v1 = acc[mt][nt][s][h * 2 + 1] + sB[c + 1];
                    pacc[mt][h] += v0 * sWaZ[c] + v1 * sWaZ[c + 1];
                    if (row0 + r < n_nodes)
                        *(float2*)&g_T[(size_t)(row0 + r) * 128 + c] = make_float2(v0, v1);
                }
            }
#pragma unroll
    for (int mt = 0; mt < 2; mt++)
#pragma unroll
        for (int h = 0; h < 2; h++) {
            float p = pacc[mt][h];
            p += __shfl_xor_sync(0xffffffffu, p, 1);
            p += __shfl_xor_sync(0xffffffffu, p, 2);
            const int r = wm + mt * 16 + (lane >> 2) + h * 8;
            if ((lane & 3) == 0) ppart[(wid & 3) * 64 + r] = p;
        }
    __syncthreads();
    if (tid < 64) {
        int row = row0 + tid;
        if (row < n_nodes)
            g_p[row] = ppart[tid] + ppart[64 + tid] + ppart[128 + tid] + ppart[192 + tid];
    }

    // ---- q[n] = self_h[n] . Wa_s  (one warp per row) ----
    for (int r = wid; r < 64; r += 8) {
        int row = row0 + r;
        if (row < n_nodes) {
            float4 v = *(const float4*)&self_h[(size_t)row * 128 + lane * 4];
            float s = v.x * sWaS[lane * 4 + 0] + v.y * sWaS[lane * 4 + 1]
                    + v.z * sWaS[lane * 4 + 2] + v.w * sWaS[lane * 4 + 3];
            s += __shfl_xor_sync(0xffffffffu, s, 16);
            s += __shfl_xor_sync(0xffffffffu, s, 8);
            s += __shfl_xor_sync(0xffffffffu, s, 4);
            s += __shfl_xor_sync(0xffffffffu, s, 2);
            s += __shfl_xor_sync(0xffffffffu, s, 1);
            if (lane == 0) g_q[row] = s;
        }
    }
}

// ============================================================================
// Kernel 2: edge streaming. Persistent warps, 8 edges / warp-iter (MLP=8),
// streaming stores keep T L2-resident.
// ============================================================================
__global__ __launch_bounds__(256)
void edge_kernel(const int* __restrict__ src_idx,
                 const int* __restrict__ dst_idx,
                 const float* __restrict__ attn_b,
                 float* __restrict__ z1,
                 float* __restrict__ e,
                 int n_edges)
{
    const int warp   = blockIdx.x * 8 + (threadIdx.x >> 5);
    const int lane   = threadIdx.x & 31;
    const int nwarps = gridDim.x * 8;
    const float ab   = __ldg(attn_b);

    for (int base = warp * 8; base < n_edges; base += nwarps * 8) {
        const int n = min(8, n_edges - base);
        int s[8];
#pragma unroll
        for (int j = 0; j < 8; j++)
            s[j] = (j < n) ? __ldg(&src_idx[base + j]) : 0;

        float4 v[8];
#pragma unroll
        for (int j = 0; j < 8; j++)
            v[j] = __ldg((const float4*)&g_T[(size_t)s[j] * 128] + lane);

#pragma unroll
        for (int j = 0; j < 8; j++)
            if (j < n)
                __stcs(((float4*)z1) + (size_t)(base + j) * 32 + lane, v[j]);

        if (lane < n) {
            int ej = base + lane;
            int ss = __ldg(&src_idx[ej]);
            int dd = __ldg(&dst_idx[ej]);
            float a = g_p[ss] + g_q[dd] + ab;
            e[ej] = (a >= 0.f) ? a : NEG_SLOPE * a;
        }
    }
}

// ============================================================================
extern "C" void kernel_launch(void* const* d_in, const int* in_sizes, int n_in,
                              void* d_out, int out_size)
{
    const float* src_h   = (const float*)d_in[0];
    const float* self_h  = (const float*)d_in[1];
    const int*   src_idx = (const int*)d_in[2];
    const int*   dst_idx = (const int*)d_in[3];
    const float* W       = (const float*)d_in[4];
    const float* b       = (const float*)d_in[5];
    const float* attn_W  = (const float*)d_in[6];
    const float* attn_b  = (const float*)d_in[7];

    int n_nodes = in_sizes[0] / 128;
    int n_edges = in_sizes[2];

    float* z1 = (float*)d_out;                    // n_edges x 128
    float* e  = z1 + (size_t)n_edges * 128;       // n_edges

    cudaFuncSetAttribute(node_gemm_kernel,
                         cudaFuncAttributeMaxDynamicSharedMemorySize, SM_TOTAL);

    prep_w_kernel<<<64, 256>>>(W);
    node_gemm_kernel<<<(n_nodes + 63) / 64, 256, SM_TOTAL>>>(src_h, self_h, b, attn_W, n_nodes);
    edge_kernel<<<1184, 256>>>(src_idx, dst_idx, attn_b, z1, e, n_edges);
}